// round 7
// baseline (speedup 1.0000x reference)
#include <cuda_runtime.h>

#define NN 50000
#define EE 800000
#define IN1 128
#define HC1 256   // H1 * CC
#define H1 4
#define CC 64
#define NEG 0.2f
#define NB_SCAN 196   // ceil(50000/256)

// ---------------- scratch (device globals; allocation-free) ----------------
__device__ float g_h1[NN * HC1];
__device__ float g_agg1[NN * HC1];
__device__ float g_h2[NN * CC];
__device__ float g_as1[NN * H1];
__device__ float g_ad1[NN * H1];
__device__ float g_as2[NN];
__device__ float g_ad2[NN];
__device__ int   g_deg[NN];
__device__ int   g_off[NN + 1];
__device__ int   g_cur[NN];
__device__ int   g_csr_src[EE];
__device__ unsigned long long g_lb[NB_SCAN];
__device__ int   g_ticket;
__device__ int   g_is64;

__device__ __forceinline__ float leaky(float v) {
    return v > 0.f ? v : NEG * v;
}

// ---- packed f32x2 helpers (sm_100+) ----
__device__ __forceinline__ unsigned long long pk2(float lo, float hi) {
    unsigned long long r;
    asm("mov.b64 %0, {%1, %2};" : "=l"(r) : "f"(lo), "f"(hi));
    return r;
}
__device__ __forceinline__ void fma2(unsigned long long& d,
                                     unsigned long long a, unsigned long long b) {
    asm("fma.rn.f32x2 %0, %1, %2, %0;" : "+l"(d) : "l"(a), "l"(b));
}
__device__ __forceinline__ void upk2(unsigned long long v, float& lo, float& hi) {
    asm("mov.b64 {%0, %1}, %2;" : "=f"(lo), "=f"(hi) : "l"(v));
}

__device__ __forceinline__ int edge_at(const void* __restrict__ ei, int idx) {
    if (g_is64) return (int)((const long long*)ei)[idx];
    return ((const int*)ei)[idx];
}

// ---------------- prep: zero state + dtype detect (fused) ----------------
__global__ void prep_kernel(const void* __restrict__ ei) {
    int i = blockIdx.x * blockDim.x + threadIdx.x;
    if (i < NN) g_deg[i] = 0;
    if (i < NB_SCAN) g_lb[i] = 0ULL;
    if (i == 0) g_ticket = 0;
    if (blockIdx.x == 0 && threadIdx.x < 32) {
        const unsigned long long* p = (const unsigned long long*)ei;
        unsigned long long a = p[threadIdx.x] | p[threadIdx.x + 32];
        unsigned ok = __ballot_sync(0xFFFFFFFF, (a >> 32) == 0ull);
        if (threadIdx.x == 0) g_is64 = (ok == 0xFFFFFFFFu) ? 1 : 0;
    }
}

__global__ void count_kernel(const void* __restrict__ ei) {
    int e = blockIdx.x * blockDim.x + threadIdx.x;
    if (e < EE) {
        int dst = edge_at(ei, EE + e);
        atomicAdd(&g_deg[dst], 1);
    }
}

// ---------------- single-pass decoupled-lookback scan ----------------
// flags in bits[63:62]: 1=partial, 2=inclusive-prefix
__global__ __launch_bounds__(256) void scan_kernel() {
    __shared__ int s_bid;
    __shared__ int s_carry;
    __shared__ int wsum[8];
    int tid = threadIdx.x;
    if (tid == 0) s_bid = atomicAdd(&g_ticket, 1);
    __syncthreads();
    int b = s_bid;
    int idx = b * 256 + tid;
    int v = (idx < NN) ? g_deg[idx] : 0;
    int lane = tid & 31, w = tid >> 5;
    int x = v;
    #pragma unroll
    for (int o = 1; o < 32; o <<= 1) {
        int t = __shfl_up_sync(0xFFFFFFFF, x, o);
        if (lane >= o) x += t;
    }
    if (lane == 31) wsum[w] = x;
    __syncthreads();
    if (tid == 0) {
        int run = 0;
        #pragma unroll
        for (int i = 0; i < 8; i++) { int t = wsum[i]; wsum[i] = run; run += t; }
        // publish
        unsigned long long pub = ((b == 0) ? (2ULL << 62) : (1ULL << 62))
                                 | (unsigned long long)(unsigned)run;
        __threadfence();
        atomicExch(&g_lb[b], pub);
        int carry = 0;
        if (b > 0) {
            int p = b - 1;
            while (true) {
                unsigned long long s = atomicAdd(&g_lb[p], 0ULL);
                unsigned f = (unsigned)(s >> 62);
                if (f == 0) continue;
                carry += (int)(s & 0xFFFFFFFFULL);
                if (f == 2) break;
                p--;
            }
            __threadfence();
            atomicExch(&g_lb[b], (2ULL << 62) |
                       (unsigned long long)(unsigned)(run + carry));
        }
        s_carry = carry;
        if (b == NB_SCAN - 1) g_off[NN] = run + carry;
    }
    __syncthreads();
    if (idx < NN) {
        int exc = x - v + wsum[w] + s_carry;
        g_off[idx] = exc;
        g_cur[idx] = exc;
    }
}

// ---------------- scatter (lean: src only) ----------------
__global__ void scatter_kernel(const void* __restrict__ ei) {
    int e = blockIdx.x * blockDim.x + threadIdx.x;
    if (e < EE) {
        int src = edge_at(ei, e);
        int dst = edge_at(ei, EE + e);
        int pos = atomicAdd(&g_cur[dst], 1);
        g_csr_src[pos] = src;
    }
}

// ------- GEMM (f32x2 packed) + fused alpha epilogue -------
template <int K, int NC, int H>
__device__ __forceinline__ void gemm_alpha_body(
    const float* __restrict__ A, const float* __restrict__ B,
    float* __restrict__ C,
    const float* __restrict__ attS, const float* __restrict__ attD,
    float* __restrict__ as_, float* __restrict__ ad_)
{
    __shared__ float As[16][128];
    __shared__ float Bs[16][64];
    int tid = threadIdx.x;         // 0..127
    int ty = tid >> 3;             // 0..15 (8 rows each)
    int tx = tid & 7;              // 0..7  (8 cols each)
    int m0 = blockIdx.x * 128;
    int hh = blockIdx.y;
    int n0 = hh * 64;

    unsigned long long acc2[4][8];
    #pragma unroll
    for (int p = 0; p < 4; p++)
        #pragma unroll
        for (int j = 0; j < 8; j++) acc2[p][j] = 0ull;

    for (int k0 = 0; k0 < K; k0 += 16) {
        {
            int gr = m0 + tid;
            float4 v[4];
            if (gr < NN) {
                const float4* ap = (const float4*)(A + (size_t)gr * K + k0);
                #pragma unroll
                for (int f = 0; f < 4; f++) v[f] = ap[f];
            } else {
                #pragma unroll
                for (int f = 0; f < 4; f++) v[f] = make_float4(0.f, 0.f, 0.f, 0.f);
            }
            #pragma unroll
            for (int f = 0; f < 4; f++) {
                As[f * 4 + 0][tid] = v[f].x;
                As[f * 4 + 1][tid] = v[f].y;
                As[f * 4 + 2][tid] = v[f].z;
                As[f * 4 + 3][tid] = v[f].w;
            }
        }
        {
            #pragma unroll
            for (int q = 0; q < 2; q++) {
                int f = tid + q * 128;
                int kr = f >> 4;
                int c4 = f & 15;
                const float4* bp = (const float4*)(B + (size_t)(k0 + kr) * NC + n0 + c4 * 4);
                *(float4*)&Bs[kr][c4 * 4] = *bp;
            }
        }
        __syncthreads();
        #pragma unroll
        for (int kk = 0; kk < 16; kk++) {
            unsigned long long ap[4];
            #pragma unroll
            for (int p = 0; p < 4; p++)
                ap[p] = *(const unsigned long long*)&As[kk][ty * 8 + 2 * p];
            float4 b0 = *(const float4*)&Bs[kk][tx * 8];
            float4 b1 = *(const float4*)&Bs[kk][tx * 8 + 4];
            unsigned long long bb[8];
            bb[0] = pk2(b0.x, b0.x); bb[1] = pk2(b0.y, b0.y);
            bb[2] = pk2(b0.z, b0.z); bb[3] = pk2(b0.w, b0.w);
            bb[4] = pk2(b1.x, b1.x); bb[5] = pk2(b1.y, b1.y);
            bb[6] = pk2(b1.z, b1.z); bb[7] = pk2(b1.w, b1.w);
            #pragma unroll
            for (int p = 0; p < 4; p++)
                #pragma unroll
                for (int j = 0; j < 8; j++)
                    fma2(acc2[p][j], ap[p], bb[j]);
        }
        __syncthreads();
    }

    float aS[8], aD[8];
    #pragma unroll
    for (int j = 0; j < 8; j++) {
        aS[j] = attS[hh * 64 + tx * 8 + j];
        aD[j] = attD[hh * 64 + tx * 8 + j];
    }

    float ds[8], dd[8];
    #pragma unroll
    for (int i = 0; i < 8; i++) { ds[i] = 0.f; dd[i] = 0.f; }

    #pragma unroll
    for (int p = 0; p < 4; p++) {
        float lo[8], hi[8];
        #pragma unroll
        for (int j = 0; j < 8; j++) upk2(acc2[p][j], lo[j], hi[j]);
        int r0 = m0 + ty * 8 + 2 * p;
        if (r0 < NN) {
            float4 u = make_float4(lo[0], lo[1], lo[2], lo[3]);
            float4 v = make_float4(lo[4], lo[5], lo[6], lo[7]);
            *(float4*)(C + (size_t)r0 * (64 * H) + n0 + tx * 8) = u;
            *(float4*)(C + (size_t)r0 * (64 * H) + n0 + tx * 8 + 4) = v;
        }
        if (r0 + 1 < NN) {
            float4 u = make_float4(hi[0], hi[1], hi[2], hi[3]);
            float4 v = make_float4(hi[4], hi[5], hi[6], hi[7]);
            *(float4*)(C + (size_t)(r0 + 1) * (64 * H) + n0 + tx * 8) = u;
            *(float4*)(C + (size_t)(r0 + 1) * (64 * H) + n0 + tx * 8 + 4) = v;
        }
        #pragma unroll
        for (int j = 0; j < 8; j++) {
            ds[2 * p]     += lo[j] * aS[j];
            dd[2 * p]     += lo[j] * aD[j];
            ds[2 * p + 1] += hi[j] * aS[j];
            dd[2 * p + 1] += hi[j] * aD[j];
        }
    }

    #pragma unroll
    for (int o = 1; o < 8; o <<= 1) {
        #pragma unroll
        for (int i = 0; i < 8; i++) {
            ds[i] += __shfl_xor_sync(0xFFFFFFFF, ds[i], o);
            dd[i] += __shfl_xor_sync(0xFFFFFFFF, dd[i], o);
        }
    }
    if (tx == 0) {
        #pragma unroll
        for (int i = 0; i < 8; i++) {
            int r = m0 + ty * 8 + i;
            if (r < NN) {
                as_[r * H + hh] = ds[i];
                ad_[r * H + hh] = dd[i];
            }
        }
    }
}

__global__ __launch_bounds__(128) void gemm1_kernel(
    const float* __restrict__ A, const float* __restrict__ B,
    const float* __restrict__ attS, const float* __restrict__ attD) {
    gemm_alpha_body<IN1, HC1, H1>(A, B, g_h1, attS, attD, g_as1, g_ad1);
}
__global__ __launch_bounds__(128) void gemm2_kernel(
    const float* __restrict__ B,
    const float* __restrict__ attS, const float* __restrict__ attD) {
    gemm_alpha_body<HC1, CC, 1>(g_agg1, B, g_h2, attS, attD, g_as2, g_ad2);
}

// ---------------- aggregation (edge weights computed inline, MLP-4) ----------------
__global__ __launch_bounds__(256) void agg1_kernel(const float* __restrict__ bias) {
    int i = blockIdx.x;
    int tid = threadIdx.x;          // 0..255
    int hh = tid >> 6;              // head (warp-uniform)
    int beg = g_off[i];
    int end = g_off[i + 1];
    float dl = g_ad1[i * H1 + hh];  // dst alpha term, loaded once
    float acc = 0.f, sw = 0.f;
    int k = beg;
    for (; k + 4 <= end; k += 4) {
        int s0 = g_csr_src[k],     s1 = g_csr_src[k + 1];
        int s2 = g_csr_src[k + 2], s3 = g_csr_src[k + 3];
        float a0 = g_as1[s0 * H1 + hh], a1 = g_as1[s1 * H1 + hh];
        float a2 = g_as1[s2 * H1 + hh], a3 = g_as1[s3 * H1 + hh];
        float v0 = g_h1[(size_t)s0 * HC1 + tid];
        float v1 = g_h1[(size_t)s1 * HC1 + tid];
        float v2 = g_h1[(size_t)s2 * HC1 + tid];
        float v3 = g_h1[(size_t)s3 * HC1 + tid];
        float w0 = expf(leaky(a0 + dl));
        float w1 = expf(leaky(a1 + dl));
        float w2 = expf(leaky(a2 + dl));
        float w3 = expf(leaky(a3 + dl));
        acc += w0 * v0 + w1 * v1 + w2 * v2 + w3 * v3;
        sw += w0 + w1 + w2 + w3;
    }
    for (; k < end; k++) {
        int s = g_csr_src[k];
        float w = expf(leaky(g_as1[s * H1 + hh] + dl));
        acc += w * g_h1[(size_t)s * HC1 + tid];
        sw += w;
    }
    float es = expf(leaky(g_as1[i * H1 + hh] + dl));
    acc += es * g_h1[(size_t)i * HC1 + tid];
    sw += es;
    float o = acc / (sw + 1e-16f) + bias[tid];
    g_agg1[(size_t)i * HC1 + tid] = fmaxf(o, 0.f);
}

__global__ __launch_bounds__(256) void agg2_kernel(const float* __restrict__ bias,
                                                   float* __restrict__ out) {
    int i = blockIdx.x * 4 + (threadIdx.x >> 6);
    int c = threadIdx.x & 63;
    if (i >= NN) return;
    int beg = g_off[i];
    int end = g_off[i + 1];
    float dl = g_ad2[i];
    float acc = 0.f, sw = 0.f;
    int k = beg;
    for (; k + 4 <= end; k += 4) {
        int s0 = g_csr_src[k],     s1 = g_csr_src[k + 1];
        int s2 = g_csr_src[k + 2], s3 = g_csr_src[k + 3];
        float a0 = g_as2[s0], a1 = g_as2[s1], a2 = g_as2[s2], a3 = g_as2[s3];
        float v0 = g_h2[(size_t)s0 * CC + c];
        float v1 = g_h2[(size_t)s1 * CC + c];
        float v2 = g_h2[(size_t)s2 * CC + c];
        float v3 = g_h2[(size_t)s3 * CC + c];
        float w0 = expf(leaky(a0 + dl));
        float w1 = expf(leaky(a1 + dl));
        float w2 = expf(leaky(a2 + dl));
        float w3 = expf(leaky(a3 + dl));
        acc += w0 * v0 + w1 * v1 + w2 * v2 + w3 * v3;
        sw += w0 + w1 + w2 + w3;
    }
    for (; k < end; k++) {
        int s = g_csr_src[k];
        float w = expf(leaky(g_as2[s] + dl));
        acc += w * g_h2[(size_t)s * CC + c];
        sw += w;
    }
    float es = expf(leaky(g_as2[i] + dl));
    acc += es * g_h2[(size_t)i * CC + c];
    sw += es;
    out[(size_t)i * CC + c] = acc / (sw + 1e-16f) + bias[c];
}

// ---------------- launch ----------------
extern "C" void kernel_launch(void* const* d_in, const int* in_sizes, int n_in,
                              void* d_out, int out_size) {
    const float* x     = (const float*)d_in[0];
    const void*  ei    = d_in[1];
    const float* W1    = (const float*)d_in[2];
    const float* asrc1 = (const float*)d_in[3];
    const float* adst1 = (const float*)d_in[4];
    const float* b1    = (const float*)d_in[5];
    const float* W2    = (const float*)d_in[6];
    const float* asrc2 = (const float*)d_in[7];
    const float* adst2 = (const float*)d_in[8];
    const float* b2    = (const float*)d_in[9];
    float* out = (float*)d_out;

    prep_kernel<<<NB_SCAN, 256>>>(ei);                 // 1
    count_kernel<<<(EE + 255) / 256, 256>>>(ei);       // 2
    scan_kernel<<<NB_SCAN, 256>>>();                   // 3
    {
        dim3 g((NN + 127) / 128, H1);
        gemm1_kernel<<<g, 128>>>(x, W1, asrc1, adst1); // 4  <- profiled slot
    }
    scatter_kernel<<<(EE + 255) / 256, 256>>>(ei);     // 5
    agg1_kernel<<<NN, 256>>>(b1);                      // 6
    {
        dim3 g((NN + 127) / 128, 1);
        gemm2_kernel<<<g, 128>>>(W2, asrc2, adst2);    // 7
    }
    agg2_kernel<<<(NN + 3) / 4, 256>>>(b2, out);       // 8
}

// round 8
// speedup vs baseline: 1.0121x; 1.0121x over previous
#include <cuda_runtime.h>

#define NN 50000
#define EE 800000
#define IN1 128
#define HC1 256   // H1 * CC
#define H1 4
#define CC 64
#define NEG 0.2f
#define NB_SCAN 196   // ceil(50000/256)

// ---------------- scratch (device globals; allocation-free) ----------------
__device__ float g_h1[NN * HC1];
__device__ float g_agg1[NN * HC1];
__device__ float g_h2[NN * CC];
__device__ float g_as1[NN * H1];
__device__ float g_ad1[NN * H1];
__device__ float g_as2[NN];
__device__ float g_ad2[NN];
__device__ int   g_deg[NN];
__device__ int   g_off[NN + 1];
__device__ int   g_cur[NN];
__device__ int   g_csr_src[EE];
__device__ unsigned long long g_lb[NB_SCAN];
__device__ int   g_ticket;
__device__ int   g_is64;

__device__ __forceinline__ float leaky(float v) {
    return v > 0.f ? v : NEG * v;
}

// ---- packed f32x2 helpers (sm_100+) ----
__device__ __forceinline__ unsigned long long pk2(float lo, float hi) {
    unsigned long long r;
    asm("mov.b64 %0, {%1, %2};" : "=l"(r) : "f"(lo), "f"(hi));
    return r;
}
__device__ __forceinline__ void fma2(unsigned long long& d,
                                     unsigned long long a, unsigned long long b) {
    asm("fma.rn.f32x2 %0, %1, %2, %0;" : "+l"(d) : "l"(a), "l"(b));
}
__device__ __forceinline__ void upk2(unsigned long long v, float& lo, float& hi) {
    asm("mov.b64 {%0, %1}, %2;" : "=f"(lo), "=f"(hi) : "l"(v));
}

__device__ __forceinline__ unsigned s2u(const void* p) {
    return (unsigned)__cvta_generic_to_shared(p);
}
__device__ __forceinline__ void cp16(unsigned dst, const void* src) {
    asm volatile("cp.async.cg.shared.global [%0], [%1], 16;" :: "r"(dst), "l"(src));
}
__device__ __forceinline__ void cp_commit() {
    asm volatile("cp.async.commit_group;" ::: "memory");
}
template <int N>
__device__ __forceinline__ void cp_wait() {
    asm volatile("cp.async.wait_group %0;" :: "n"(N) : "memory");
}

__device__ __forceinline__ int edge_at(const void* __restrict__ ei, int idx) {
    if (g_is64) return (int)((const long long*)ei)[idx];
    return ((const int*)ei)[idx];
}

// ---------------- prep: zero state + dtype detect (fused) ----------------
__global__ void prep_kernel(const void* __restrict__ ei) {
    int i = blockIdx.x * blockDim.x + threadIdx.x;
    if (i < NN) g_deg[i] = 0;
    if (i < NB_SCAN) g_lb[i] = 0ULL;
    if (i == 0) g_ticket = 0;
    if (blockIdx.x == 0 && threadIdx.x < 32) {
        const unsigned long long* p = (const unsigned long long*)ei;
        unsigned long long a = p[threadIdx.x] | p[threadIdx.x + 32];
        unsigned ok = __ballot_sync(0xFFFFFFFF, (a >> 32) == 0ull);
        if (threadIdx.x == 0) g_is64 = (ok == 0xFFFFFFFFu) ? 1 : 0;
    }
}

__global__ void count_kernel(const void* __restrict__ ei) {
    int e = blockIdx.x * blockDim.x + threadIdx.x;
    if (e < EE) {
        int dst = edge_at(ei, EE + e);
        atomicAdd(&g_deg[dst], 1);
    }
}

// ---------------- single-pass decoupled-lookback scan ----------------
__global__ __launch_bounds__(256) void scan_kernel() {
    __shared__ int s_bid;
    __shared__ int s_carry;
    __shared__ int wsum[8];
    int tid = threadIdx.x;
    if (tid == 0) s_bid = atomicAdd(&g_ticket, 1);
    __syncthreads();
    int b = s_bid;
    int idx = b * 256 + tid;
    int v = (idx < NN) ? g_deg[idx] : 0;
    int lane = tid & 31, w = tid >> 5;
    int x = v;
    #pragma unroll
    for (int o = 1; o < 32; o <<= 1) {
        int t = __shfl_up_sync(0xFFFFFFFF, x, o);
        if (lane >= o) x += t;
    }
    if (lane == 31) wsum[w] = x;
    __syncthreads();
    if (tid == 0) {
        int run = 0;
        #pragma unroll
        for (int i = 0; i < 8; i++) { int t = wsum[i]; wsum[i] = run; run += t; }
        unsigned long long pub = ((b == 0) ? (2ULL << 62) : (1ULL << 62))
                                 | (unsigned long long)(unsigned)run;
        __threadfence();
        atomicExch(&g_lb[b], pub);
        int carry = 0;
        if (b > 0) {
            int p = b - 1;
            while (true) {
                unsigned long long s = atomicAdd(&g_lb[p], 0ULL);
                unsigned f = (unsigned)(s >> 62);
                if (f == 0) continue;
                carry += (int)(s & 0xFFFFFFFFULL);
                if (f == 2) break;
                p--;
            }
            __threadfence();
            atomicExch(&g_lb[b], (2ULL << 62) |
                       (unsigned long long)(unsigned)(run + carry));
        }
        s_carry = carry;
        if (b == NB_SCAN - 1) g_off[NN] = run + carry;
    }
    __syncthreads();
    if (idx < NN) {
        int exc = x - v + wsum[w] + s_carry;
        g_off[idx] = exc;
        g_cur[idx] = exc;
    }
}

__global__ void scatter_kernel(const void* __restrict__ ei) {
    int e = blockIdx.x * blockDim.x + threadIdx.x;
    if (e < EE) {
        int src = edge_at(ei, e);
        int dst = edge_at(ei, EE + e);
        int pos = atomicAdd(&g_cur[dst], 1);
        g_csr_src[pos] = src;
    }
}

// ------- 2-stage pipelined GEMM (f32x2) + fused alpha epilogue -------
// Tile 128x64, 128 threads, microtile 8x8. B via cp.async; A via reg-staged STS.
template <int K, int NC, int H>
__device__ __forceinline__ void gemm_alpha_body(
    const float* __restrict__ A, const float* __restrict__ B,
    float* __restrict__ C,
    const float* __restrict__ attS, const float* __restrict__ attD,
    float* __restrict__ as_, float* __restrict__ ad_)
{
    constexpr int NT = K / 16;
    __shared__ float As[2][16][128];
    __shared__ float Bs[2][16][64];
    int tid = threadIdx.x;         // 0..127
    int ty = tid >> 3;             // 0..15
    int tx = tid & 7;              // 0..7
    int m0 = blockIdx.x * 128;
    int hh = blockIdx.y;
    int n0 = hh * 64;

    int arow = m0 + tid;
    if (arow >= NN) arow = NN - 1;           // clamped (never stored for OOB rows)
    const float* aptr = A + (size_t)arow * K;
    int bkr = tid >> 4;                       // 0..7 (we issue 2 rows sets)
    int bc4 = tid & 15;

    unsigned long long acc2[4][8];
    #pragma unroll
    for (int p = 0; p < 4; p++)
        #pragma unroll
        for (int j = 0; j < 8; j++) acc2[p][j] = 0ull;

    // prologue: stage 0
    float4 v[4];
    #pragma unroll
    for (int f = 0; f < 4; f++) v[f] = ((const float4*)aptr)[f];
    #pragma unroll
    for (int f = 0; f < 4; f++) {
        As[0][f * 4 + 0][tid] = v[f].x;
        As[0][f * 4 + 1][tid] = v[f].y;
        As[0][f * 4 + 2][tid] = v[f].z;
        As[0][f * 4 + 3][tid] = v[f].w;
    }
    #pragma unroll
    for (int q = 0; q < 2; q++) {
        int f = tid + q * 128;
        int kr = f >> 4;
        int c4 = f & 15;
        cp16(s2u(&Bs[0][kr][c4 * 4]), B + (size_t)kr * NC + n0 + c4 * 4);
    }
    cp_commit();

    for (int kt = 0; kt < NT; kt++) {
        int cur = kt & 1;
        int nxt = cur ^ 1;
        bool more = (kt + 1 < NT);
        if (more) {
            int k0 = (kt + 1) * 16;
            #pragma unroll
            for (int f = 0; f < 4; f++) v[f] = ((const float4*)(aptr + k0))[f];
            #pragma unroll
            for (int q = 0; q < 2; q++) {
                int f = tid + q * 128;
                int kr = f >> 4;
                int c4 = f & 15;
                cp16(s2u(&Bs[nxt][kr][c4 * 4]), B + (size_t)(k0 + kr) * NC + n0 + c4 * 4);
            }
            cp_commit();
            cp_wait<1>();
        } else {
            cp_wait<0>();
        }
        __syncthreads();
        #pragma unroll
        for (int kk = 0; kk < 16; kk++) {
            unsigned long long ap[4];
            #pragma unroll
            for (int p = 0; p < 4; p++)
                ap[p] = *(const unsigned long long*)&As[cur][kk][ty * 8 + 2 * p];
            float4 b0 = *(const float4*)&Bs[cur][kk][tx * 8];
            float4 b1 = *(const float4*)&Bs[cur][kk][tx * 8 + 4];
            unsigned long long bb[8];
            bb[0] = pk2(b0.x, b0.x); bb[1] = pk2(b0.y, b0.y);
            bb[2] = pk2(b0.z, b0.z); bb[3] = pk2(b0.w, b0.w);
            bb[4] = pk2(b1.x, b1.x); bb[5] = pk2(b1.y, b1.y);
            bb[6] = pk2(b1.z, b1.z); bb[7] = pk2(b1.w, b1.w);
            #pragma unroll
            for (int p = 0; p < 4; p++)
                #pragma unroll
                for (int j = 0; j < 8; j++)
                    fma2(acc2[p][j], ap[p], bb[j]);
        }
        if (more) {
            #pragma unroll
            for (int f = 0; f < 4; f++) {
                As[nxt][f * 4 + 0][tid] = v[f].x;
                As[nxt][f * 4 + 1][tid] = v[f].y;
                As[nxt][f * 4 + 2][tid] = v[f].z;
                As[nxt][f * 4 + 3][tid] = v[f].w;
            }
        }
        __syncthreads();
    }

    float aS[8], aD[8];
    #pragma unroll
    for (int j = 0; j < 8; j++) {
        aS[j] = attS[hh * 64 + tx * 8 + j];
        aD[j] = attD[hh * 64 + tx * 8 + j];
    }

    float ds[8], dd[8];
    #pragma unroll
    for (int i = 0; i < 8; i++) { ds[i] = 0.f; dd[i] = 0.f; }

    #pragma unroll
    for (int p = 0; p < 4; p++) {
        float lo[8], hi[8];
        #pragma unroll
        for (int j = 0; j < 8; j++) upk2(acc2[p][j], lo[j], hi[j]);
        int r0 = m0 + ty * 8 + 2 * p;
        if (r0 < NN) {
            float4 u = make_float4(lo[0], lo[1], lo[2], lo[3]);
            float4 w2 = make_float4(lo[4], lo[5], lo[6], lo[7]);
            *(float4*)(C + (size_t)r0 * (64 * H) + n0 + tx * 8) = u;
            *(float4*)(C + (size_t)r0 * (64 * H) + n0 + tx * 8 + 4) = w2;
        }
        if (r0 + 1 < NN) {
            float4 u = make_float4(hi[0], hi[1], hi[2], hi[3]);
            float4 w2 = make_float4(hi[4], hi[5], hi[6], hi[7]);
            *(float4*)(C + (size_t)(r0 + 1) * (64 * H) + n0 + tx * 8) = u;
            *(float4*)(C + (size_t)(r0 + 1) * (64 * H) + n0 + tx * 8 + 4) = w2;
        }
        #pragma unroll
        for (int j = 0; j < 8; j++) {
            ds[2 * p]     += lo[j] * aS[j];
            dd[2 * p]     += lo[j] * aD[j];
            ds[2 * p + 1] += hi[j] * aS[j];
            dd[2 * p + 1] += hi[j] * aD[j];
        }
    }

    #pragma unroll
    for (int o = 1; o < 8; o <<= 1) {
        #pragma unroll
        for (int i = 0; i < 8; i++) {
            ds[i] += __shfl_xor_sync(0xFFFFFFFF, ds[i], o);
            dd[i] += __shfl_xor_sync(0xFFFFFFFF, dd[i], o);
        }
    }
    if (tx == 0) {
        #pragma unroll
        for (int i = 0; i < 8; i++) {
            int r = m0 + ty * 8 + i;
            if (r < NN) {
                as_[r * H + hh] = ds[i];
                ad_[r * H + hh] = dd[i];
            }
        }
    }
}

__global__ __launch_bounds__(128) void gemm1_kernel(
    const float* __restrict__ A, const float* __restrict__ B,
    const float* __restrict__ attS, const float* __restrict__ attD) {
    gemm_alpha_body<IN1, HC1, H1>(A, B, g_h1, attS, attD, g_as1, g_ad1);
}
__global__ __launch_bounds__(128) void gemm2_kernel(
    const float* __restrict__ B,
    const float* __restrict__ attS, const float* __restrict__ attD) {
    gemm_alpha_body<HC1, CC, 1>(g_agg1, B, g_h2, attS, attD, g_as2, g_ad2);
}

// ---------------- aggregation (inline weights, MLP-8) ----------------
__global__ __launch_bounds__(256) void agg1_kernel(const float* __restrict__ bias) {
    int i = blockIdx.x;
    int tid = threadIdx.x;
    int hh = tid >> 6;
    int beg = g_off[i];
    int end = g_off[i + 1];
    float dl = g_ad1[i * H1 + hh];
    float acc = 0.f, sw = 0.f;
    int k = beg;
    for (; k + 8 <= end; k += 8) {
        int s[8];
        #pragma unroll
        for (int u = 0; u < 8; u++) s[u] = g_csr_src[k + u];
        float a[8], vv[8];
        #pragma unroll
        for (int u = 0; u < 8; u++) a[u] = g_as1[s[u] * H1 + hh];
        #pragma unroll
        for (int u = 0; u < 8; u++) vv[u] = g_h1[(size_t)s[u] * HC1 + tid];
        #pragma unroll
        for (int u = 0; u < 8; u++) {
            float w = expf(leaky(a[u] + dl));
            acc += w * vv[u];
            sw += w;
        }
    }
    for (; k < end; k++) {
        int s = g_csr_src[k];
        float w = expf(leaky(g_as1[s * H1 + hh] + dl));
        acc += w * g_h1[(size_t)s * HC1 + tid];
        sw += w;
    }
    float es = expf(leaky(g_as1[i * H1 + hh] + dl));
    acc += es * g_h1[(size_t)i * HC1 + tid];
    sw += es;
    float o = acc / (sw + 1e-16f) + bias[tid];
    g_agg1[(size_t)i * HC1 + tid] = fmaxf(o, 0.f);
}

__global__ __launch_bounds__(256) void agg2_kernel(const float* __restrict__ bias,
                                                   float* __restrict__ out) {
    int i = blockIdx.x * 4 + (threadIdx.x >> 6);
    int c = threadIdx.x & 63;
    if (i >= NN) return;
    int beg = g_off[i];
    int end = g_off[i + 1];
    float dl = g_ad2[i];
    float acc = 0.f, sw = 0.f;
    int k = beg;
    for (; k + 8 <= end; k += 8) {
        int s[8];
        #pragma unroll
        for (int u = 0; u < 8; u++) s[u] = g_csr_src[k + u];
        float a[8], vv[8];
        #pragma unroll
        for (int u = 0; u < 8; u++) a[u] = g_as2[s[u]];
        #pragma unroll
        for (int u = 0; u < 8; u++) vv[u] = g_h2[(size_t)s[u] * CC + c];
        #pragma unroll
        for (int u = 0; u < 8; u++) {
            float w = expf(leaky(a[u] + dl));
            acc += w * vv[u];
            sw += w;
        }
    }
    for (; k < end; k++) {
        int s = g_csr_src[k];
        float w = expf(leaky(g_as2[s] + dl));
        acc += w * g_h2[(size_t)s * CC + c];
        sw += w;
    }
    float es = expf(leaky(g_as2[i] + dl));
    acc += es * g_h2[(size_t)i * CC + c];
    sw += es;
    out[(size_t)i * CC + c] = acc / (sw + 1e-16f) + bias[c];
}

// ---------------- launch ----------------
extern "C" void kernel_launch(void* const* d_in, const int* in_sizes, int n_in,
                              void* d_out, int out_size) {
    const float* x     = (const float*)d_in[0];
    const void*  ei    = d_in[1];
    const float* W1    = (const float*)d_in[2];
    const float* asrc1 = (const float*)d_in[3];
    const float* adst1 = (const float*)d_in[4];
    const float* b1    = (const float*)d_in[5];
    const float* W2    = (const float*)d_in[6];
    const float* asrc2 = (const float*)d_in[7];
    const float* adst2 = (const float*)d_in[8];
    const float* b2    = (const float*)d_in[9];
    float* out = (float*)d_out;

    prep_kernel<<<NB_SCAN, 256>>>(ei);                 // 1
    count_kernel<<<(EE + 255) / 256, 256>>>(ei);       // 2
    scan_kernel<<<NB_SCAN, 256>>>();                   // 3
    {
        dim3 g((NN + 127) / 128, H1);
        gemm1_kernel<<<g, 128>>>(x, W1, asrc1, adst1); // 4  <- profiled slot
    }
    scatter_kernel<<<(EE + 255) / 256, 256>>>(ei);     // 5
    agg1_kernel<<<NN, 256>>>(b1);                      // 6
    {
        dim3 g((NN + 127) / 128, 1);
        gemm2_kernel<<<g, 128>>>(W2, asrc2, adst2);    // 7
    }
    agg2_kernel<<<(NN + 3) / 4, 256>>>(b2, out);       // 8
}

// round 10
// speedup vs baseline: 1.2727x; 1.2574x over previous
#include <cuda_runtime.h>

#define NN 50000
#define EE 800000
#define IN1 128
#define HC1 256   // H1 * CC
#define H1 4
#define CC 64
#define NEG 0.2f
#define NB_SCAN 196           // ceil(50000/256)
#define GEMM1_BLKS 1564       // 391 m-tiles * 4 heads
#define SCAT_BLKS 782         // 1024 edges each

// ---------------- scratch (device globals; allocation-free) ----------------
__device__ float g_h1[NN * HC1];
__device__ float g_agg1[NN * HC1];
__device__ float g_h2[NN * CC];
__device__ float g_as1[NN * H1];
__device__ float g_ad1[NN * H1];
__device__ float g_as2[NN];
__device__ float g_ad2[NN];
__device__ int   g_deg[NN];
__device__ int   g_off[NN + 1];
__device__ int   g_cur[NN];
__device__ int   g_csr_src[EE];
__device__ unsigned long long g_lb[NB_SCAN];
__device__ int   g_ticket;
__device__ int   g_is64;

__device__ __forceinline__ float leaky(float v) {
    return v > 0.f ? v : NEG * v;
}

// ---- packed f32x2 helpers (sm_100+) ----
__device__ __forceinline__ unsigned long long pk2(float lo, float hi) {
    unsigned long long r;
    asm("mov.b64 %0, {%1, %2};" : "=l"(r) : "f"(lo), "f"(hi));
    return r;
}
__device__ __forceinline__ void fma2(unsigned long long& d,
                                     unsigned long long a, unsigned long long b) {
    asm("fma.rn.f32x2 %0, %1, %2, %0;" : "+l"(d) : "l"(a), "l"(b));
}
__device__ __forceinline__ void upk2(unsigned long long v, float& lo, float& hi) {
    asm("mov.b64 {%0, %1}, %2;" : "=f"(lo), "=f"(hi) : "l"(v));
}

__device__ __forceinline__ unsigned s2u(const void* p) {
    return (unsigned)__cvta_generic_to_shared(p);
}
__device__ __forceinline__ void cp16(unsigned dst, const void* src) {
    asm volatile("cp.async.cg.shared.global [%0], [%1], 16;" :: "r"(dst), "l"(src));
}
__device__ __forceinline__ void cp_commit() {
    asm volatile("cp.async.commit_group;" ::: "memory");
}
template <int N>
__device__ __forceinline__ void cp_wait() {
    asm volatile("cp.async.wait_group %0;" :: "n"(N) : "memory");
}

__device__ __forceinline__ int edge_at(const void* __restrict__ ei, int idx) {
    if (g_is64) return (int)((const long long*)ei)[idx];
    return ((const int*)ei)[idx];
}

// ---------------- prep: zero state + dtype detect (fused) ----------------
__global__ void prep_kernel(const void* __restrict__ ei) {
    int i = blockIdx.x * blockDim.x + threadIdx.x;
    if (i < NN) g_deg[i] = 0;
    if (i < NB_SCAN) g_lb[i] = 0ULL;
    if (i == 0) g_ticket = 0;
    if (blockIdx.x == 0 && threadIdx.x < 32) {
        const unsigned long long* p = (const unsigned long long*)ei;
        unsigned long long a = p[threadIdx.x] | p[threadIdx.x + 32];
        unsigned ok = __ballot_sync(0xFFFFFFFF, (a >> 32) == 0ull);
        if (threadIdx.x == 0) g_is64 = (ok == 0xFFFFFFFFu) ? 1 : 0;
    }
}

__global__ void count_kernel(const void* __restrict__ ei) {
    int base = (blockIdx.x * blockDim.x + threadIdx.x) * 4;
    #pragma unroll
    for (int u = 0; u < 4; u++) {
        int e = base + u;
        if (e < EE) atomicAdd(&g_deg[edge_at(ei, EE + e)], 1);
    }
}

// ---------------- single-pass decoupled-lookback scan ----------------
__global__ __launch_bounds__(256) void scan_kernel() {
    __shared__ int s_bid;
    __shared__ int s_carry;
    __shared__ int wsum[8];
    int tid = threadIdx.x;
    if (tid == 0) s_bid = atomicAdd(&g_ticket, 1);
    __syncthreads();
    int b = s_bid;
    int idx = b * 256 + tid;
    int v = (idx < NN) ? g_deg[idx] : 0;
    int lane = tid & 31, w = tid >> 5;
    int x = v;
    #pragma unroll
    for (int o = 1; o < 32; o <<= 1) {
        int t = __shfl_up_sync(0xFFFFFFFF, x, o);
        if (lane >= o) x += t;
    }
    if (lane == 31) wsum[w] = x;
    __syncthreads();
    if (tid == 0) {
        int run = 0;
        #pragma unroll
        for (int i = 0; i < 8; i++) { int t = wsum[i]; wsum[i] = run; run += t; }
        unsigned long long pub = ((b == 0) ? (2ULL << 62) : (1ULL << 62))
                                 | (unsigned long long)(unsigned)run;
        __threadfence();
        atomicExch(&g_lb[b], pub);
        int carry = 0;
        if (b > 0) {
            int p = b - 1;
            while (true) {
                unsigned long long s = atomicAdd(&g_lb[p], 0ULL);
                unsigned f = (unsigned)(s >> 62);
                if (f == 0) continue;
                carry += (int)(s & 0xFFFFFFFFULL);
                if (f == 2) break;
                p--;
            }
            __threadfence();
            atomicExch(&g_lb[b], (2ULL << 62) |
                       (unsigned long long)(unsigned)(run + carry));
        }
        s_carry = carry;
        if (b == NB_SCAN - 1) g_off[NN] = run + carry;
    }
    __syncthreads();
    if (idx < NN) {
        int exc = x - v + wsum[w] + s_carry;
        g_off[idx] = exc;
        g_cur[idx] = exc;
    }
}

// ------- GEMM core (f32x2, 2-stage cp.async pipeline) + fused alpha -------
template <int K, int NC, int H>
__device__ __forceinline__ void gemm_alpha_body(
    int m0, int hh,
    const float* __restrict__ A, const float* __restrict__ B,
    float* __restrict__ C,
    const float* __restrict__ attS, const float* __restrict__ attD,
    float* __restrict__ as_, float* __restrict__ ad_)
{
    constexpr int NT = K / 16;
    __shared__ float As[2][16][128];
    __shared__ float Bs[2][16][64];
    int tid = threadIdx.x;         // 0..127
    int ty = tid >> 3;             // 0..15
    int tx = tid & 7;              // 0..7
    int n0 = hh * 64;

    int arow = m0 + tid;
    if (arow >= NN) arow = NN - 1;
    const float* aptr = A + (size_t)arow * K;

    unsigned long long acc2[4][8];
    #pragma unroll
    for (int p = 0; p < 4; p++)
        #pragma unroll
        for (int j = 0; j < 8; j++) acc2[p][j] = 0ull;

    float4 v[4];
    #pragma unroll
    for (int f = 0; f < 4; f++) v[f] = ((const float4*)aptr)[f];
    #pragma unroll
    for (int f = 0; f < 4; f++) {
        As[0][f * 4 + 0][tid] = v[f].x;
        As[0][f * 4 + 1][tid] = v[f].y;
        As[0][f * 4 + 2][tid] = v[f].z;
        As[0][f * 4 + 3][tid] = v[f].w;
    }
    #pragma unroll
    for (int q = 0; q < 2; q++) {
        int f = tid + q * 128;
        int kr = f >> 4;
        int c4 = f & 15;
        cp16(s2u(&Bs[0][kr][c4 * 4]), B + (size_t)kr * NC + n0 + c4 * 4);
    }
    cp_commit();

    for (int kt = 0; kt < NT; kt++) {
        int cur = kt & 1;
        int nxt = cur ^ 1;
        bool more = (kt + 1 < NT);
        if (more) {
            int k0 = (kt + 1) * 16;
            #pragma unroll
            for (int f = 0; f < 4; f++) v[f] = ((const float4*)(aptr + k0))[f];
            #pragma unroll
            for (int q = 0; q < 2; q++) {
                int f = tid + q * 128;
                int kr = f >> 4;
                int c4 = f & 15;
                cp16(s2u(&Bs[nxt][kr][c4 * 4]), B + (size_t)(k0 + kr) * NC + n0 + c4 * 4);
            }
            cp_commit();
            cp_wait<1>();
        } else {
            cp_wait<0>();
        }
        __syncthreads();
        #pragma unroll
        for (int kk = 0; kk < 16; kk++) {
            unsigned long long ap[4];
            #pragma unroll
            for (int p = 0; p < 4; p++)
                ap[p] = *(const unsigned long long*)&As[cur][kk][ty * 8 + 2 * p];
            float4 b0 = *(const float4*)&Bs[cur][kk][tx * 8];
            float4 b1 = *(const float4*)&Bs[cur][kk][tx * 8 + 4];
            unsigned long long bb[8];
            bb[0] = pk2(b0.x, b0.x); bb[1] = pk2(b0.y, b0.y);
            bb[2] = pk2(b0.z, b0.z); bb[3] = pk2(b0.w, b0.w);
            bb[4] = pk2(b1.x, b1.x); bb[5] = pk2(b1.y, b1.y);
            bb[6] = pk2(b1.z, b1.z); bb[7] = pk2(b1.w, b1.w);
            #pragma unroll
            for (int p = 0; p < 4; p++)
                #pragma unroll
                for (int j = 0; j < 8; j++)
                    fma2(acc2[p][j], ap[p], bb[j]);
        }
        if (more) {
            #pragma unroll
            for (int f = 0; f < 4; f++) {
                As[nxt][f * 4 + 0][tid] = v[f].x;
                As[nxt][f * 4 + 1][tid] = v[f].y;
                As[nxt][f * 4 + 2][tid] = v[f].z;
                As[nxt][f * 4 + 3][tid] = v[f].w;
            }
        }
        __syncthreads();
    }

    float aS[8], aD[8];
    #pragma unroll
    for (int j = 0; j < 8; j++) {
        aS[j] = attS[hh * 64 + tx * 8 + j];
        aD[j] = attD[hh * 64 + tx * 8 + j];
    }

    float ds[8], dd[8];
    #pragma unroll
    for (int i = 0; i < 8; i++) { ds[i] = 0.f; dd[i] = 0.f; }

    #pragma unroll
    for (int p = 0; p < 4; p++) {
        float lo[8], hi[8];
        #pragma unroll
        for (int j = 0; j < 8; j++) upk2(acc2[p][j], lo[j], hi[j]);
        int r0 = m0 + ty * 8 + 2 * p;
        if (r0 < NN) {
            float4 u = make_float4(lo[0], lo[1], lo[2], lo[3]);
            float4 w2 = make_float4(lo[4], lo[5], lo[6], lo[7]);
            *(float4*)(C + (size_t)r0 * (64 * H) + n0 + tx * 8) = u;
            *(float4*)(C + (size_t)r0 * (64 * H) + n0 + tx * 8 + 4) = w2;
        }
        if (r0 + 1 < NN) {
            float4 u = make_float4(hi[0], hi[1], hi[2], hi[3]);
            float4 w2 = make_float4(hi[4], hi[5], hi[6], hi[7]);
            *(float4*)(C + (size_t)(r0 + 1) * (64 * H) + n0 + tx * 8) = u;
            *(float4*)(C + (size_t)(r0 + 1) * (64 * H) + n0 + tx * 8 + 4) = w2;
        }
        #pragma unroll
        for (int j = 0; j < 8; j++) {
            ds[2 * p]     += lo[j] * aS[j];
            dd[2 * p]     += lo[j] * aD[j];
            ds[2 * p + 1] += hi[j] * aS[j];
            dd[2 * p + 1] += hi[j] * aD[j];
        }
    }

    #pragma unroll
    for (int o = 1; o < 8; o <<= 1) {
        #pragma unroll
        for (int i = 0; i < 8; i++) {
            ds[i] += __shfl_xor_sync(0xFFFFFFFF, ds[i], o);
            dd[i] += __shfl_xor_sync(0xFFFFFFFF, dd[i], o);
        }
    }
    if (tx == 0) {
        #pragma unroll
        for (int i = 0; i < 8; i++) {
            int r = m0 + ty * 8 + i;
            if (r < NN) {
                as_[r * H + hh] = ds[i];
                ad_[r * H + hh] = dd[i];
            }
        }
    }
}

// fused: gemm1 blocks + scatter blocks in one launch (scatter hides under gemm)
__global__ __launch_bounds__(128) void gemm1_scatter_kernel(
    const float* __restrict__ A, const float* __restrict__ B,
    const float* __restrict__ attS, const float* __restrict__ attD,
    const void* __restrict__ ei)
{
    int bid = blockIdx.x;
    if (bid < GEMM1_BLKS) {
        gemm_alpha_body<IN1, HC1, H1>((bid >> 2) * 128, bid & 3,
                                      A, B, g_h1, attS, attD, g_as1, g_ad1);
    } else {
        int base = (bid - GEMM1_BLKS) * 1024;
        #pragma unroll
        for (int t = 0; t < 8; t++) {
            int e = base + t * 128 + threadIdx.x;
            if (e < EE) {
                int src = edge_at(ei, e);
                int dst = edge_at(ei, EE + e);
                int pos = atomicAdd(&g_cur[dst], 1);
                g_csr_src[pos] = src;
            }
        }
    }
}

__global__ __launch_bounds__(128) void gemm2_kernel(
    const float* __restrict__ B,
    const float* __restrict__ attS, const float* __restrict__ attD) {
    gemm_alpha_body<HC1, CC, 1>(blockIdx.x * 128, 0,
                                g_agg1, B, g_h2, attS, attD, g_as2, g_ad2);
}

// ---------------- aggregation (lane-dedup'd __expf weights, MLP-8) --------
__global__ __launch_bounds__(256) void agg1_kernel(const float* __restrict__ bias) {
    int i = blockIdx.x;
    int tid = threadIdx.x;
    int hh = tid >> 6;              // warp-uniform
    int lane = tid & 31;
    int beg = g_off[i];
    int end = g_off[i + 1];
    float dl = g_ad1[i * H1 + hh];
    float acc = 0.f, sw = 0.f;
    int k = beg;
    for (; k + 8 <= end; k += 8) {
        // lane u (u<8) owns edge k+u: loads src + computes weight once per warp
        int s_l = g_csr_src[k + (lane & 7)];
        float w_l = (lane < 8) ? __expf(leaky(g_as1[s_l * H1 + hh] + dl)) : 0.f;
        int su[8];
        float wu[8];
        #pragma unroll
        for (int u = 0; u < 8; u++) {
            su[u] = __shfl_sync(0xFFFFFFFF, s_l, u);
            wu[u] = __shfl_sync(0xFFFFFFFF, w_l, u);
        }
        float vv[8];
        #pragma unroll
        for (int u = 0; u < 8; u++) vv[u] = g_h1[(size_t)su[u] * HC1 + tid];
        #pragma unroll
        for (int u = 0; u < 8; u++) {
            acc += wu[u] * vv[u];
            sw += wu[u];
        }
    }
    for (; k < end; k++) {
        int s = g_csr_src[k];
        float w = __expf(leaky(g_as1[s * H1 + hh] + dl));
        acc += w * g_h1[(size_t)s * HC1 + tid];
        sw += w;
    }
    float es = __expf(leaky(g_as1[i * H1 + hh] + dl));
    acc += es * g_h1[(size_t)i * HC1 + tid];
    sw += es;
    float o = acc / (sw + 1e-16f) + bias[tid];
    g_agg1[(size_t)i * HC1 + tid] = fmaxf(o, 0.f);
}

__global__ __launch_bounds__(256) void agg2_kernel(const float* __restrict__ bias,
                                                   float* __restrict__ out) {
    int i = blockIdx.x * 4 + (threadIdx.x >> 6);   // node (warp-uniform)
    int c = threadIdx.x & 63;
    int lane = threadIdx.x & 31;
    if (i >= NN) return;
    int beg = g_off[i];
    int end = g_off[i + 1];
    float dl = g_ad2[i];
    float acc = 0.f, sw = 0.f;
    int k = beg;
    for (; k + 8 <= end; k += 8) {
        int s_l = g_csr_src[k + (lane & 7)];
        float w_l = (lane < 8) ? __expf(leaky(g_as2[s_l] + dl)) : 0.f;
        int su[8];
        float wu[8];
        #pragma unroll
        for (int u = 0; u < 8; u++) {
            su[u] = __shfl_sync(0xFFFFFFFF, s_l, u);
            wu[u] = __shfl_sync(0xFFFFFFFF, w_l, u);
        }
        float vv[8];
        #pragma unroll
        for (int u = 0; u < 8; u++) vv[u] = g_h2[(size_t)su[u] * CC + c];
        #pragma unroll
        for (int u = 0; u < 8; u++) {
            acc += wu[u] * vv[u];
            sw += wu[u];
        }
    }
    for (; k < end; k++) {
        int s = g_csr_src[k];
        float w = __expf(leaky(g_as2[s] + dl));
        acc += w * g_h2[(size_t)s * CC + c];
        sw += w;
    }
    float es = __expf(leaky(g_as2[i] + dl));
    acc += es * g_h2[(size_t)i * CC + c];
    sw += es;
    out[(size_t)i * CC + c] = acc / (sw + 1e-16f) + bias[c];
}

// ---------------- launch ----------------
extern "C" void kernel_launch(void* const* d_in, const int* in_sizes, int n_in,
                              void* d_out, int out_size) {
    const float* x     = (const float*)d_in[0];
    const void*  ei    = d_in[1];
    const float* W1    = (const float*)d_in[2];
    const float* asrc1 = (const float*)d_in[3];
    const float* adst1 = (const float*)d_in[4];
    const float* b1    = (const float*)d_in[5];
    const float* W2    = (const float*)d_in[6];
    const float* asrc2 = (const float*)d_in[7];
    const float* adst2 = (const float*)d_in[8];
    const float* b2    = (const float*)d_in[9];
    float* out = (float*)d_out;

    prep_kernel<<<NB_SCAN, 256>>>(ei);                          // 1
    count_kernel<<<(EE / 4 + 255) / 256, 256>>>(ei);            // 2
    scan_kernel<<<NB_SCAN, 256>>>();                            // 3
    gemm1_scatter_kernel<<<GEMM1_BLKS + SCAT_BLKS, 128>>>(      // 4 <- profiled
        x, W1, asrc1, adst1, ei);
    agg1_kernel<<<NN, 256>>>(b1);                               // 5
    gemm2_kernel<<<(NN + 127) / 128, 128>>>(W2, asrc2, adst2);  // 6
    agg2_kernel<<<(NN + 3) / 4, 256>>>(b2, out);                // 7
}

// round 12
// speedup vs baseline: 1.5894x; 1.2489x over previous
#include <cuda_runtime.h>

#define NN 50000
#define EE 800000
#define IN1 128
#define HC1 256   // H1 * CC
#define H1 4
#define CC 64
#define NEG 0.2f
#define NB_SCAN 196           // ceil(50000/256)
#define GEMM1_BLKS 1564       // 391 m-tiles * 4 heads
#define SCAT_BLKS 782         // 1024 edges each

// ---------------- scratch (device globals; allocation-free) ----------------
__device__ float g_h1[NN * HC1];
__device__ float g_agg1[NN * HC1];
__device__ float g_h2[NN * CC];
__device__ float g_as1[NN * H1];
__device__ float g_ad1[NN * H1];
__device__ float g_as2[NN];
__device__ float g_ad2[NN];
__device__ int   g_deg[NN];
__device__ int   g_off[NN + 1];
__device__ int   g_cur[NN];
__device__ int   g_csr_src[EE];
__device__ unsigned long long g_lb[NB_SCAN];
__device__ int   g_ticket;
__device__ int   g_is64;

__device__ __forceinline__ float leaky(float v) {
    return v > 0.f ? v : NEG * v;
}

// ---- packed f32x2 helpers (sm_100+) ----
__device__ __forceinline__ unsigned long long pk2(float lo, float hi) {
    unsigned long long r;
    asm("mov.b64 %0, {%1, %2};" : "=l"(r) : "f"(lo), "f"(hi));
    return r;
}
__device__ __forceinline__ void fma2(unsigned long long& d,
                                     unsigned long long a, unsigned long long b) {
    asm("fma.rn.f32x2 %0, %1, %2, %0;" : "+l"(d) : "l"(a), "l"(b));
}
__device__ __forceinline__ void upk2(unsigned long long v, float& lo, float& hi) {
    asm("mov.b64 {%0, %1}, %2;" : "=f"(lo), "=f"(hi) : "l"(v));
}

__device__ __forceinline__ unsigned s2u(const void* p) {
    return (unsigned)__cvta_generic_to_shared(p);
}
__device__ __forceinline__ void cp16(unsigned dst, const void* src) {
    asm volatile("cp.async.cg.shared.global [%0], [%1], 16;" :: "r"(dst), "l"(src));
}
__device__ __forceinline__ void cp_commit() {
    asm volatile("cp.async.commit_group;" ::: "memory");
}
template <int N>
__device__ __forceinline__ void cp_wait() {
    asm volatile("cp.async.wait_group %0;" :: "n"(N) : "memory");
}

__device__ __forceinline__ int edge_at(const void* __restrict__ ei, int idx) {
    if (g_is64) return (int)((const long long*)ei)[idx];
    return ((const int*)ei)[idx];
}

// ---------------- prep: zero state + dtype detect (fused) ----------------
__global__ void prep_kernel(const void* __restrict__ ei) {
    int i = blockIdx.x * blockDim.x + threadIdx.x;
    if (i < NN) g_deg[i] = 0;
    if (i < NB_SCAN) g_lb[i] = 0ULL;
    if (i == 0) g_ticket = 0;
    if (blockIdx.x == 0 && threadIdx.x < 32) {
        const unsigned long long* p = (const unsigned long long*)ei;
        unsigned long long a = p[threadIdx.x] | p[threadIdx.x + 32];
        unsigned ok = __ballot_sync(0xFFFFFFFF, (a >> 32) == 0ull);
        if (threadIdx.x == 0) g_is64 = (ok == 0xFFFFFFFFu) ? 1 : 0;
    }
}

__global__ void count_kernel(const void* __restrict__ ei) {
    int base = (blockIdx.x * blockDim.x + threadIdx.x) * 8;
    #pragma unroll
    for (int u = 0; u < 8; u++) {
        int e = base + u;
        if (e < EE) atomicAdd(&g_deg[edge_at(ei, EE + e)], 1);
    }
}

// ---------------- single-pass decoupled-lookback scan ----------------
__global__ __launch_bounds__(256) void scan_kernel() {
    __shared__ int s_bid;
    __shared__ int s_carry;
    __shared__ int wsum[8];
    int tid = threadIdx.x;
    if (tid == 0) s_bid = atomicAdd(&g_ticket, 1);
    __syncthreads();
    int b = s_bid;
    int idx = b * 256 + tid;
    int v = (idx < NN) ? g_deg[idx] : 0;
    int lane = tid & 31, w = tid >> 5;
    int x = v;
    #pragma unroll
    for (int o = 1; o < 32; o <<= 1) {
        int t = __shfl_up_sync(0xFFFFFFFF, x, o);
        if (lane >= o) x += t;
    }
    if (lane == 31) wsum[w] = x;
    __syncthreads();
    if (tid == 0) {
        int run = 0;
        #pragma unroll
        for (int i = 0; i < 8; i++) { int t = wsum[i]; wsum[i] = run; run += t; }
        unsigned long long pub = ((b == 0) ? (2ULL << 62) : (1ULL << 62))
                                 | (unsigned long long)(unsigned)run;
        __threadfence();
        atomicExch(&g_lb[b], pub);
        int carry = 0;
        if (b > 0) {
            int p = b - 1;
            while (true) {
                unsigned long long s = atomicAdd(&g_lb[p], 0ULL);
                unsigned f = (unsigned)(s >> 62);
                if (f == 0) continue;
                carry += (int)(s & 0xFFFFFFFFULL);
                if (f == 2) break;
                p--;
            }
            __threadfence();
            atomicExch(&g_lb[b], (2ULL << 62) |
                       (unsigned long long)(unsigned)(run + carry));
        }
        s_carry = carry;
        if (b == NB_SCAN - 1) g_off[NN] = run + carry;
    }
    __syncthreads();
    if (idx < NN) {
        int exc = x - v + wsum[w] + s_carry;
        g_off[idx] = exc;
        g_cur[idx] = exc;
    }
}

// ------- GEMM core (f32x2, 2-stage cp.async pipeline) + fused alpha -------
template <int K, int NC, int H>
__device__ __forceinline__ void gemm_alpha_body(
    int m0, int hh,
    const float* __restrict__ A, const float* __restrict__ B,
    float* __restrict__ C,
    const float* __restrict__ attS, const float* __restrict__ attD,
    float* __restrict__ as_, float* __restrict__ ad_)
{
    constexpr int NT = K / 16;
    __shared__ float As[2][16][128];
    __shared__ float Bs[2][16][64];
    int tid = threadIdx.x;         // 0..127
    int ty = tid >> 3;             // 0..15
    int tx = tid & 7;              // 0..7
    int n0 = hh * 64;

    int arow = m0 + tid;
    if (arow >= NN) arow = NN - 1;
    const float* aptr = A + (size_t)arow * K;

    unsigned long long acc2[4][8];
    #pragma unroll
    for (int p = 0; p < 4; p++)
        #pragma unroll
        for (int j = 0; j < 8; j++) acc2[p][j] = 0ull;

    float4 v[4];
    #pragma unroll
    for (int f = 0; f < 4; f++) v[f] = ((const float4*)aptr)[f];
    #pragma unroll
    for (int f = 0; f < 4; f++) {
        As[0][f * 4 + 0][tid] = v[f].x;
        As[0][f * 4 + 1][tid] = v[f].y;
        As[0][f * 4 + 2][tid] = v[f].z;
        As[0][f * 4 + 3][tid] = v[f].w;
    }
    #pragma unroll
    for (int q = 0; q < 2; q++) {
        int f = tid + q * 128;
        int kr = f >> 4;
        int c4 = f & 15;
        cp16(s2u(&Bs[0][kr][c4 * 4]), B + (size_t)kr * NC + n0 + c4 * 4);
    }
    cp_commit();

    for (int kt = 0; kt < NT; kt++) {
        int cur = kt & 1;
        int nxt = cur ^ 1;
        bool more = (kt + 1 < NT);
        if (more) {
            int k0 = (kt + 1) * 16;
            #pragma unroll
            for (int f = 0; f < 4; f++) v[f] = ((const float4*)(aptr + k0))[f];
            #pragma unroll
            for (int q = 0; q < 2; q++) {
                int f = tid + q * 128;
                int kr = f >> 4;
                int c4 = f & 15;
                cp16(s2u(&Bs[nxt][kr][c4 * 4]), B + (size_t)(k0 + kr) * NC + n0 + c4 * 4);
            }
            cp_commit();
            cp_wait<1>();
        } else {
            cp_wait<0>();
        }
        __syncthreads();
        #pragma unroll
        for (int kk = 0; kk < 16; kk++) {
            unsigned long long ap[4];
            #pragma unroll
            for (int p = 0; p < 4; p++)
                ap[p] = *(const unsigned long long*)&As[cur][kk][ty * 8 + 2 * p];
            float4 b0 = *(const float4*)&Bs[cur][kk][tx * 8];
            float4 b1 = *(const float4*)&Bs[cur][kk][tx * 8 + 4];
            unsigned long long bb[8];
            bb[0] = pk2(b0.x, b0.x); bb[1] = pk2(b0.y, b0.y);
            bb[2] = pk2(b0.z, b0.z); bb[3] = pk2(b0.w, b0.w);
            bb[4] = pk2(b1.x, b1.x); bb[5] = pk2(b1.y, b1.y);
            bb[6] = pk2(b1.z, b1.z); bb[7] = pk2(b1.w, b1.w);
            #pragma unroll
            for (int p = 0; p < 4; p++)
                #pragma unroll
                for (int j = 0; j < 8; j++)
                    fma2(acc2[p][j], ap[p], bb[j]);
        }
        if (more) {
            #pragma unroll
            for (int f = 0; f < 4; f++) {
                As[nxt][f * 4 + 0][tid] = v[f].x;
                As[nxt][f * 4 + 1][tid] = v[f].y;
                As[nxt][f * 4 + 2][tid] = v[f].z;
                As[nxt][f * 4 + 3][tid] = v[f].w;
            }
        }
        __syncthreads();
    }

    float aS[8], aD[8];
    #pragma unroll
    for (int j = 0; j < 8; j++) {
        aS[j] = attS[hh * 64 + tx * 8 + j];
        aD[j] = attD[hh * 64 + tx * 8 + j];
    }

    float ds[8], dd[8];
    #pragma unroll
    for (int i = 0; i < 8; i++) { ds[i] = 0.f; dd[i] = 0.f; }

    #pragma unroll
    for (int p = 0; p < 4; p++) {
        float lo[8], hi[8];
        #pragma unroll
        for (int j = 0; j < 8; j++) upk2(acc2[p][j], lo[j], hi[j]);
        int r0 = m0 + ty * 8 + 2 * p;
        if (r0 < NN) {
            float4 u = make_float4(lo[0], lo[1], lo[2], lo[3]);
            float4 w2 = make_float4(lo[4], lo[5], lo[6], lo[7]);
            *(float4*)(C + (size_t)r0 * (64 * H) + n0 + tx * 8) = u;
            *(float4*)(C + (size_t)r0 * (64 * H) + n0 + tx * 8 + 4) = w2;
        }
        if (r0 + 1 < NN) {
            float4 u = make_float4(hi[0], hi[1], hi[2], hi[3]);
            float4 w2 = make_float4(hi[4], hi[5], hi[6], hi[7]);
            *(float4*)(C + (size_t)(r0 + 1) * (64 * H) + n0 + tx * 8) = u;
            *(float4*)(C + (size_t)(r0 + 1) * (64 * H) + n0 + tx * 8 + 4) = w2;
        }
        #pragma unroll
        for (int j = 0; j < 8; j++) {
            ds[2 * p]     += lo[j] * aS[j];
            dd[2 * p]     += lo[j] * aD[j];
            ds[2 * p + 1] += hi[j] * aS[j];
            dd[2 * p + 1] += hi[j] * aD[j];
        }
    }

    #pragma unroll
    for (int o = 1; o < 8; o <<= 1) {
        #pragma unroll
        for (int i = 0; i < 8; i++) {
            ds[i] += __shfl_xor_sync(0xFFFFFFFF, ds[i], o);
            dd[i] += __shfl_xor_sync(0xFFFFFFFF, dd[i], o);
        }
    }
    if (tx == 0) {
        #pragma unroll
        for (int i = 0; i < 8; i++) {
            int r = m0 + ty * 8 + i;
            if (r < NN) {
                as_[r * H + hh] = ds[i];
                ad_[r * H + hh] = dd[i];
            }
        }
    }
}

// fused: gemm1 blocks + scatter blocks in one launch (scatter hides under gemm)
__global__ __launch_bounds__(128) void gemm1_scatter_kernel(
    const float* __restrict__ A, const float* __restrict__ B,
    const float* __restrict__ attS, const float* __restrict__ attD,
    const void* __restrict__ ei)
{
    int bid = blockIdx.x;
    if (bid < GEMM1_BLKS) {
        gemm_alpha_body<IN1, HC1, H1>((bid >> 2) * 128, bid & 3,
                                      A, B, g_h1, attS, attD, g_as1, g_ad1);
    } else {
        int base = (bid - GEMM1_BLKS) * 1024;
        #pragma unroll
        for (int t = 0; t < 8; t++) {
            int e = base + t * 128 + threadIdx.x;
            if (e < EE) {
                int src = edge_at(ei, e);
                int dst = edge_at(ei, EE + e);
                int pos = atomicAdd(&g_cur[dst], 1);
                g_csr_src[pos] = src;
            }
        }
    }
}

__global__ __launch_bounds__(128) void gemm2_kernel(
    const float* __restrict__ B,
    const float* __restrict__ attS, const float* __restrict__ attD) {
    gemm_alpha_body<HC1, CC, 1>(blockIdx.x * 128, 0,
                                g_agg1, B, g_h2, attS, attD, g_as2, g_ad2);
}

// -------- aggregation layer1: float4, 4 nodes/block, exp-dedup ----------
__global__ __launch_bounds__(256) void agg1_kernel(const float* __restrict__ bias) {
    int tid = threadIdx.x;
    int i = blockIdx.x * 4 + (tid >> 6);     // node
    int c4 = tid & 63;                       // float4 channel index (x4 = channel)
    int hh = c4 >> 4;                        // this thread's head
    int lane = tid & 31;
    int head_base = ((tid & 63) >> 5) * 2;   // first head covered by this warp
    int hcomp = head_base + ((lane >> 3) & 1);  // head computed by weight lanes
    int beg = g_off[i];
    int end = g_off[i + 1];
    float dl  = g_ad1[i * H1 + hh];
    float dlc = g_ad1[i * H1 + hcomp];
    float4 acc = make_float4(0.f, 0.f, 0.f, 0.f);
    float sw = 0.f;
    int srclb = (lane >> 4) << 3;            // 0 or 8: weight-lane group for my head
    int k = beg;
    for (; k + 8 <= end; k += 8) {
        int s_l = g_csr_src[k + (lane & 7)];
        float w_l = (lane < 16) ? __expf(leaky(g_as1[s_l * H1 + hcomp] + dlc)) : 0.f;
        int su[8]; float wu[8];
        #pragma unroll
        for (int u = 0; u < 8; u++) {
            su[u] = __shfl_sync(0xFFFFFFFF, s_l, u);
            wu[u] = __shfl_sync(0xFFFFFFFF, w_l, srclb + u);
        }
        float4 vv[8];
        #pragma unroll
        for (int u = 0; u < 8; u++)
            vv[u] = *(const float4*)&g_h1[(size_t)su[u] * HC1 + c4 * 4];
        #pragma unroll
        for (int u = 0; u < 8; u++) {
            acc.x += wu[u] * vv[u].x;
            acc.y += wu[u] * vv[u].y;
            acc.z += wu[u] * vv[u].z;
            acc.w += wu[u] * vv[u].w;
            sw += wu[u];
        }
    }
    for (; k < end; k++) {
        int s = g_csr_src[k];
        float w = __expf(leaky(g_as1[s * H1 + hh] + dl));
        float4 vv = *(const float4*)&g_h1[(size_t)s * HC1 + c4 * 4];
        acc.x += w * vv.x; acc.y += w * vv.y;
        acc.z += w * vv.z; acc.w += w * vv.w;
        sw += w;
    }
    float es = __expf(leaky(g_as1[i * H1 + hh] + dl));
    {
        float4 vv = *(const float4*)&g_h1[(size_t)i * HC1 + c4 * 4];
        acc.x += es * vv.x; acc.y += es * vv.y;
        acc.z += es * vv.z; acc.w += es * vv.w;
        sw += es;
    }
    float inv = 1.f / (sw + 1e-16f);
    float4 bv = *(const float4*)&bias[c4 * 4];
    float4 o;
    o.x = fmaxf(acc.x * inv + bv.x, 0.f);
    o.y = fmaxf(acc.y * inv + bv.y, 0.f);
    o.z = fmaxf(acc.z * inv + bv.z, 0.f);
    o.w = fmaxf(acc.w * inv + bv.w, 0.f);
    *(float4*)&g_agg1[(size_t)i * HC1 + c4 * 4] = o;
}

// -------- aggregation layer2: float4, 16 nodes/block, exp-dedup ---------
__global__ __launch_bounds__(256) void agg2_kernel(const float* __restrict__ bias,
                                                   float* __restrict__ out) {
    int tid = threadIdx.x;
    int i = blockIdx.x * 16 + (tid >> 4);    // node (16 lanes each)
    int c4 = tid & 15;                       // float4 channel index
    int lane = tid & 31;
    int grp = lane >> 4;                     // node-subgroup within warp
    unsigned gmask = 0xFFFFu << (grp * 16);
    int glane = lane & 15;
    int beg = g_off[i];
    int end = g_off[i + 1];
    float dl = g_ad2[i];
    float4 acc = make_float4(0.f, 0.f, 0.f, 0.f);
    float sw = 0.f;
    int k = beg;
    for (; k + 8 <= end; k += 8) {
        int s_l = g_csr_src[k + (glane & 7)];
        float w_l = (glane < 8) ? __expf(leaky(g_as2[s_l] + dl)) : 0.f;
        int su[8]; float wu[8];
        #pragma unroll
        for (int u = 0; u < 8; u++) {
            su[u] = __shfl_sync(gmask, s_l, grp * 16 + u);
            wu[u] = __shfl_sync(gmask, w_l, grp * 16 + u);
        }
        float4 vv[8];
        #pragma unroll
        for (int u = 0; u < 8; u++)
            vv[u] = *(const float4*)&g_h2[(size_t)su[u] * CC + c4 * 4];
        #pragma unroll
        for (int u = 0; u < 8; u++) {
            acc.x += wu[u] * vv[u].x;
            acc.y += wu[u] * vv[u].y;
            acc.z += wu[u] * vv[u].z;
            acc.w += wu[u] * vv[u].w;
            sw += wu[u];
        }
    }
    for (; k < end; k++) {
        int s = g_csr_src[k];
        float w = __expf(leaky(g_as2[s] + dl));
        float4 vv = *(const float4*)&g_h2[(size_t)s * CC + c4 * 4];
        acc.x += w * vv.x; acc.y += w * vv.y;
        acc.z += w * vv.z; acc.w += w * vv.w;
        sw += w;
    }
    float es = __expf(leaky(g_as2[i] + dl));
    {
        float4 vv = *(const float4*)&g_h2[(size_t)i * CC + c4 * 4];
        acc.x += es * vv.x; acc.y += es * vv.y;
        acc.z += es * vv.z; acc.w += es * vv.w;
        sw += es;
    }
    float inv = 1.f / (sw + 1e-16f);
    float4 bv = *(const float4*)&bias[c4 * 4];
    float4 o;
    o.x = acc.x * inv + bv.x;
    o.y = acc.y * inv + bv.y;
    o.z = acc.z * inv + bv.z;
    o.w = acc.w * inv + bv.w;
    *(float4*)&out[(size_t)i * CC + c4 * 4] = o;
}

// ---------------- launch ----------------
extern "C" void kernel_launch(void* const* d_in, const int* in_sizes, int n_in,
                              void* d_out, int out_size) {
    const float* x     = (const float*)d_in[0];
    const void*  ei    = d_in[1];
    const float* W1    = (const float*)d_in[2];
    const float* asrc1 = (const float*)d_in[3];
    const float* adst1 = (const float*)d_in[4];
    const float* b1    = (const float*)d_in[5];
    const float* W2    = (const float*)d_in[6];
    const float* asrc2 = (const float*)d_in[7];
    const float* adst2 = (const float*)d_in[8];
    const float* b2    = (const float*)d_in[9];
    float* out = (float*)d_out;

    prep_kernel<<<NB_SCAN, 256>>>(ei);                          // 1
    count_kernel<<<(EE / 8 + 255) / 256, 256>>>(ei);            // 2
    scan_kernel<<<NB_SCAN, 256>>>();                            // 3
    gemm1_scatter_kernel<<<GEMM1_BLKS + SCAT_BLKS, 128>>>(      // 4 <- profiled
        x, W1, asrc1, adst1, ei);
    agg1_kernel<<<NN / 4, 256>>>(b1);                           // 5
    gemm2_kernel<<<(NN + 127) / 128, 128>>>(W2, asrc2, adst2);  // 6
    agg2_kernel<<<NN / 16, 256>>>(b2, out);                     // 7
}